// round 8
// baseline (speedup 1.0000x reference)
#include <cuda_runtime.h>
#include <cstdint>

#define T_STEPS 256
#define BATCH   128
#define DIN     1024
#define HID     1024
#define NGATE   4096  // 4*HID
#define NBLK    128

// Scratch (device globals; no allocation allowed in kernel_launch).
__device__ float g_G[(size_t)T_STEPS * BATCH * NGATE];   // x@Wx + b (512 MB)
__device__ float g_xA[(size_t)T_STEPS * BATCH * DIN];    // x, tf32-rounded, A-fragment tile order (128 MB)
__device__ float g_WxB[(size_t)DIN * NGATE];             // Wx, tf32-rounded, B-fragment tile order (16 MB)
__device__ float g_h[2][BATCH * HID];                    // double-buffered hidden (tf32-rounded)
__device__ float g_c[BATCH * HID];                       // cell state
__device__ unsigned g_cnt;                               // barrier arrive counter
__device__ volatile unsigned g_gen;                      // barrier generation

// ---------------- helpers ----------------

__device__ __forceinline__ float f2tf32(float x) {
    uint32_t u;
    asm("cvt.rna.tf32.f32 %0, %1;" : "=r"(u) : "f"(x));
    return __uint_as_float(u);
}

__device__ __forceinline__ void mma_tf32(float c[4], const uint32_t a[4], const uint32_t b[2]) {
    asm volatile(
        "mma.sync.aligned.m16n8k8.row.col.f32.tf32.tf32.f32 "
        "{%0,%1,%2,%3}, {%4,%5,%6,%7}, {%8,%9}, {%0,%1,%2,%3};"
        : "+f"(c[0]), "+f"(c[1]), "+f"(c[2]), "+f"(c[3])
        : "r"(a[0]), "r"(a[1]), "r"(a[2]), "r"(a[3]), "r"(b[0]), "r"(b[1]));
}

__device__ __forceinline__ void cp_async16(uint32_t dst_smem, const void* src) {
    asm volatile("cp.async.ca.shared.global [%0], [%1], 16;" :: "r"(dst_smem), "l"(src));
}

__device__ __forceinline__ float sigmoidf_fast(float x) {
    x = fminf(fmaxf(x, -30.f), 30.f);
    return __fdividef(1.f, 1.f + __expf(-x));
}

__device__ __forceinline__ float tanhf_fast(float x) {
    x = fminf(fmaxf(x, -15.f), 15.f);
    float e = __expf(2.f * x);
    return __fdividef(e - 1.f, e + 1.f);
}

// Software grid barrier. All NBLK blocks co-resident (1 block/SM, 128<148).
__device__ __forceinline__ void grid_sync(unsigned step) {
    __syncthreads();
    if (threadIdx.x == 0) {
        __threadfence();
        unsigned a = atomicAdd(&g_cnt, 1u);
        if (a == gridDim.x - 1) {
            g_cnt = 0;
            __threadfence();
            g_gen = step + 1;
        } else {
            while (g_gen < step + 1) __nanosleep(32);
        }
        __threadfence();
    }
    __syncthreads();
}

// ---------------- init state + barrier ----------------

__global__ void init_state(const float* __restrict__ csh) {
    int idx = blockIdx.x * blockDim.x + threadIdx.x;
    if (idx == 0) { g_cnt = 0; g_gen = 0; }
    if (idx < BATCH * HID) {
        int b = idx / HID, j = idx % HID;
        g_c[idx]    = csh[b * 2 * HID + j];                  // cell (full precision)
        g_h[0][idx] = f2tf32(csh[b * 2 * HID + HID + j]);    // hidden (pre-rounded for GEMM)
    }
}

// ---------------- prep: permute+round x and Wx into fragment tile order ----
// A tile (128 rows x 32 k): float idx = k8*1024 + wm*256 + mt*128 + lane*4 + j
//   lane=(g,t4): g=lane>>2, t4=lane&3; j: 0=(h0,s0) 1=(h1,s0) 2=(h0,s1) 3=(h1,s1)
//   row = wm*32 + mt*16 + h8*8 + g ; k = k8*8 + s*4 + t4
__global__ void prep_xA(const float* __restrict__ x) {
    __shared__ float tl[128 * 33];
    int ki = blockIdx.x, mi = blockIdx.y;
    int tid = threadIdx.x;  // 256
    for (int i = 0; i < 16; i++) {
        int e = tid + i * 256, r = e >> 5, c = e & 31;
        tl[r * 33 + c] = x[(size_t)(mi * 128 + r) * DIN + ki * 32 + c];
    }
    __syncthreads();
    size_t base = ((size_t)mi * 32 + ki) << 12;  // *4096
    for (int i = 0; i < 4; i++) {
        int o = tid + i * 256;           // float4 index 0..1023
        int lane = o & 31, mt = (o >> 5) & 1, wm = (o >> 6) & 3, k8 = o >> 8;
        int g = lane >> 2, t4 = lane & 3;
        int r0 = wm * 32 + mt * 16 + g, r1 = r0 + 8;
        int ka = k8 * 8 + t4, kb = ka + 4;
        float4 v;
        v.x = f2tf32(tl[r0 * 33 + ka]);
        v.y = f2tf32(tl[r1 * 33 + ka]);
        v.z = f2tf32(tl[r0 * 33 + kb]);
        v.w = f2tf32(tl[r1 * 33 + kb]);
        ((float4*)(g_xA + base))[o] = v;
    }
}

// B tile (32 k x 128 n): float4 idx: lane=o&31, w=(o>>5)&3, wn=(o>>7)&1, k8=o>>8
//   components = (nt=2w,s0),(2w,s1),(2w+1,s0),(2w+1,s1); col = wn*64+nt*8+g; k = k8*8+t4+s*4
__global__ void prep_WxB(const float* __restrict__ Wx) {
    __shared__ float tl[32 * 129];
    int ni = blockIdx.x, ki = blockIdx.y;
    int tid = threadIdx.x;  // 256
    for (int i = 0; i < 16; i++) {
        int e = tid + i * 256, r = e >> 7, c = e & 127;
        tl[r * 129 + c] = Wx[(size_t)(ki * 32 + r) * NGATE + ni * 128 + c];
    }
    __syncthreads();
    size_t base = ((size_t)ki * 32 + ni) << 12;
    for (int i = 0; i < 4; i++) {
        int o = tid + i * 256;
        int lane = o & 31, w = (o >> 5) & 3, wn = (o >> 7) & 1, k8 = o >> 8;
        int g = lane >> 2, t4 = lane & 3;
        int c0 = wn * 64 + (2 * w) * 8 + g, c1 = c0 + 8;
        int ka = k8 * 8 + t4, kb = ka + 4;
        float4 v;
        v.x = f2tf32(tl[ka * 129 + c0]);
        v.y = f2tf32(tl[kb * 129 + c0]);
        v.z = f2tf32(tl[ka * 129 + c1]);
        v.w = f2tf32(tl[kb * 129 + c1]);
        ((float4*)(g_WxB + base))[o] = v;
    }
}

// ---------------- pre-GEMM: G = x @ Wx + bias ----------------
// Tile 128x128x32; fragment-ordered tiles; 6 LDS.128 per 16 mma; 3-stage cp.async.

#define PG_STAGE_FLOATS 8192       // A 4096 + B 4096 = 32 KB
#define PG_STAGES 3
#define PG_SMEM_BYTES (PG_STAGES * PG_STAGE_FLOATS * 4)  // 96 KB

__device__ __forceinline__ void pg_fill(uint32_t sstage, int mi, int ni, int kt, int tid) {
#pragma unroll
    for (int i = 0; i < 4; i++) {
        int o = tid + i * 256;
        cp_async16(sstage + (uint32_t)o * 16, g_xA + (((size_t)mi * 32 + kt) << 12) + o * 4);
    }
#pragma unroll
    for (int i = 0; i < 4; i++) {
        int o = tid + i * 256;
        cp_async16(sstage + 16384 + (uint32_t)o * 16, g_WxB + (((size_t)kt * 32 + ni) << 12) + o * 4);
    }
}

__global__ __launch_bounds__(256, 2) void pregemm(const float* __restrict__ bias) {
    extern __shared__ float sm[];
    const uint32_t sbase = (uint32_t)__cvta_generic_to_shared(sm);

    const int tid  = threadIdx.x;
    const int warp = tid >> 5, lane = tid & 31;
    const int g  = lane >> 2, t4 = lane & 3;
    const int wm = warp >> 1, wn = warp & 1;
    const int ni = blockIdx.x, mi = blockIdx.y;
    const int m0 = mi * 128, n0 = ni * 128;

    float acc[2][8][4];
#pragma unroll
    for (int a = 0; a < 2; a++)
#pragma unroll
        for (int b = 0; b < 8; b++)
#pragma unroll
            for (int c = 0; c < 4; c++) acc[a][b][c] = 0.f;

    pg_fill(sbase, mi, ni, 0, tid);
    asm volatile("cp.async.commit_group;");
    pg_fill(sbase + PG_STAGE_FLOATS * 4, mi, ni, 1, tid);
    asm volatile("cp.async.commit_group;");

    for (int kt = 0; kt < 32; kt++) {
        asm volatile("cp.async.wait_group 1;");
        __syncthreads();

        if (kt + 2 < 32)
            pg_fill(sbase + (uint32_t)((kt + 2) % PG_STAGES) * PG_STAGE_FLOATS * 4,
                    mi, ni, kt + 2, tid);
        asm volatile("cp.async.commit_group;");

        const float* st  = sm + (kt % PG_STAGES) * PG_STAGE_FLOATS;
        const float* stA = st;
        const float* stB = st + 4096;
#pragma unroll
        for (int k8 = 0; k8 < 4; k8++) {
            float4 fa0 = *(const float4*)&stA[k8 * 1024 + wm * 256 + lane * 4];
            float4 fa1 = *(const float4*)&stA[k8 * 1024 + wm * 256 + 128 + lane * 4];
            uint32_t a0[4] = {__float_as_uint(fa0.x), __float_as_uint(fa0.y),
                              __float_as_uint(fa0.z), __float_as_uint(fa0.w)};
            uint32_t a1[4] = {__float_as_uint(fa1.x), __float_as_uint(fa1.y),
                              __float_as_uint(fa1.z), __float_as_uint(fa1.w)};
#pragma unroll
            for (int w = 0; w < 4; w++) {
                float4 fb = *(const float4*)&stB[k8 * 1024 + wn * 512 + w * 128 + lane * 4];
                uint32_t b0[2] = {__float_as_uint(fb.x), __float_as_uint(fb.y)};
                uint32_t b1[2] = {__float_as_uint(fb.z), __float_as_uint(fb.w)};
                mma_tf32(acc[0][2 * w],     a0, b0);
                mma_tf32(acc[1][2 * w],     a1, b0);
                mma_tf32(acc[0][2 * w + 1], a0, b1);
                mma_tf32(acc[1][2 * w + 1], a1, b1);
            }
        }
    }

#pragma unroll
    for (int mt = 0; mt < 2; mt++) {
#pragma unroll
        for (int nt = 0; nt < 8; nt++) {
            int r = m0 + wm * 32 + mt * 16 + g;
            int c = n0 + wn * 64 + nt * 8 + 2 * t4;
            float b0 = bias[c], b1 = bias[c + 1];
            float2 v0 = make_float2(acc[mt][nt][0] + b0, acc[mt][nt][1] + b1);
            float2 v1 = make_float2(acc[mt][nt][2] + b0, acc[mt][nt][3] + b1);
            *(float2*)&g_G[(size_t)r * NGATE + c]       = v0;
            *(float2*)&g_G[(size_t)(r + 8) * NGATE + c] = v1;
        }
    }
}

// ---------------- persistent recurrence ----------------
// 128 blocks, 256 threads (8 warps). Block b owns gate-columns [8b,8b+8) of
// each gate. Wh fragments resident in SMEM (128 KB). A fragments loaded
// DIRECTLY from g_h via ld.global.cg with ring-8 prefetch (no staging).
// Mask ({0,1}) applied as epilogue scale on the recurrent accumulator.

#define BFRAG_FLOATS 32768       // 128 kblocks * 256
#define LS_SMEM_BYTES (BFRAG_FLOATS * 4)  // 128 KB

__global__ __launch_bounds__(256, 1) void lstm_persistent(
        const float* __restrict__ mask,
        const float* __restrict__ Wh,
        float* __restrict__ out_hs) {
    extern __shared__ float smem[];
    float* Bfrag = smem;

    const int tid  = threadIdx.x;
    const int warp = tid >> 5, lane = tid & 31;
    const int g  = lane >> 2, t4 = lane & 3;
    const int j0 = blockIdx.x * 8;
    const int rb = warp * 16;
    const int colb = j0 + 2 * t4;

    // ---- preload Wh fragments (once per launch) ----
    for (int idx = tid; idx < BFRAG_FLOATS; idx += 256) {
        int kb     = idx >> 8;
        int within = idx & 255;
        int q      = within >> 7;
        int rest   = within & 127;
        int lane_i = rest >> 2;
        int sub    = rest & 3;
        int gate   = q * 2 + (sub >> 1);
        int s      = sub & 1;
        int g8     = lane_i >> 2;
        int t4v    = lane_i & 3;
        int k      = kb * 8 + s * 4 + t4v;
        Bfrag[idx] = f2tf32(Wh[(size_t)k * NGATE + gate * HID + j0 + g8]);
    }
    __syncthreads();

    // per-step scalars for step 0
    float em0, em1;
    float2 pG[4][2];
    {
        em0 = 1.0f - __ldg(&mask[rb + g]);
        em1 = 1.0f - __ldg(&mask[rb + g + 8]);
#pragma unroll
        for (int r = 0; r < 2; r++) {
            size_t gb = ((size_t)(rb + g + r * 8)) * NGATE + colb;
#pragma unroll
            for (int gate = 0; gate < 4; gate++)
                pG[gate][r] = __ldg((const float2*)&g_G[gb + gate * HID]);
        }
    }

    for (int t = 0; t < T_STEPS; t++) {
        const float* __restrict__ h_in  = g_h[t & 1];
        float*       __restrict__ h_out = g_h[(t + 1) & 1];
        const float* r0 = h_in + (rb + g) * HID + t4;
        const float* r1 = r0 + 8 * HID;

        float nem0 = 0.f, nem1 = 0.f;
        float2 nG[4][2];
#pragma unroll
        for (int gate = 0; gate < 4; gate++) {
            nG[gate][0] = make_float2(0.f, 0.f);
            nG[gate][1] = make_float2(0.f, 0.f);
        }

        float acc[4][4];
#pragma unroll
        for (int a = 0; a < 4; a++)
#pragma unroll
            for (int c = 0; c < 4; c++) acc[a][c] = 0.f;

        // ring-8 A prefetch (32 outstanding LDG.cg per warp)
        float ar[8][4];
#pragma unroll
        for (int p = 0; p < 8; p++) {
            int kf = p * 8;
            ar[p][0] = __ldcg(r0 + kf);
            ar[p][1] = __ldcg(r1 + kf);
            ar[p][2] = __ldcg(r0 + kf + 4);
            ar[p][3] = __ldcg(r1 + kf + 4);
        }

#pragma unroll 8
        for (int kb8 = 0; kb8 < 128; kb8++) {
            int slot = kb8 & 7;
            uint32_t afr[4] = {__float_as_uint(ar[slot][0]), __float_as_uint(ar[slot][1]),
                               __float_as_uint(ar[slot][2]), __float_as_uint(ar[slot][3])};
            if (kb8 < 120) {
                int kf = (kb8 + 8) * 8;
                ar[slot][0] = __ldcg(r0 + kf);
                ar[slot][1] = __ldcg(r1 + kf);
                ar[slot][2] = __ldcg(r0 + kf + 4);
                ar[slot][3] = __ldcg(r1 + kf + 4);
            }
            if (kb8 == 64 && t + 1 < T_STEPS) {
                const float* nmrow = mask + (size_t)(t + 1) * BATCH;
                nem0 = 1.0f - __ldg(&nmrow[rb + g]);
                nem1 = 1.0f - __ldg(&nmrow[rb + g + 8]);
#pragma unroll
                for (int r = 0; r < 2; r++) {
                    size_t gb = ((size_t)(t + 1) * BATCH + rb + g + r * 8) * NGATE + colb;
#pragma unroll
                    for (int gate = 0; gate < 4; gate++)
                        nG[gate][r] = __ldg((const float2*)&g_G[gb + gate * HID]);
                }
            }
            const float* Bb = Bfrag + kb8 * 256;
            float4 bA = *(const float4*)&Bb[lane * 4];        // gates 0,1
            float4 bB = *(const float4*)&Bb[128 + lane * 4];  // gates 2,3
            uint32_t b0[2] = {__float_as_uint(bA.x), __float_as_uint(bA.y)};
            uint32_t b1[2] = {__float_as_uint(bA.z), __float_as_uint(bA.w)};
            uint32_t b2[2] = {__float_as_uint(bB.x), __float_as_uint(bB.y)};
            uint32_t b3[2] = {__float_as_uint(bB.z), __float_as_uint(bB.w)};
            mma_tf32(acc[0], afr, b0);
            mma_tf32(acc[1], afr, b1);
            mma_tf32(acc[2], afr, b2);
            mma_tf32(acc[3], afr, b3);
        }

        // epilogue: mask-scale recurrent term, LSTM pointwise, writes
#pragma unroll
        for (int r = 0; r < 2; r++) {
            int row = rb + g + r * 8;
            float em = r ? em1 : em0;
            float2 cp = *(const float2*)&g_c[row * HID + colb];
            float iv0 = em * acc[0][2 * r]     + pG[0][r].x;
            float iv1 = em * acc[0][2 * r + 1] + pG[0][r].y;
            float fv0 = em * acc[1][2 * r]     + pG[1][r].x;
            float fv1 = em * acc[1][2 * r + 1] + pG[1][r].y;
            float ov0 = em * acc[2][2 * r]     + pG[2][r].x;
            float ov1 = em * acc[2][2 * r + 1] + pG[2][r].y;
            float gv0 = em * acc[3][2 * r]     + pG[3][r].x;
            float gv1 = em * acc[3][2 * r + 1] + pG[3][r].y;
            float cn0 = sigmoidf_fast(fv0) * (cp.x * em) + sigmoidf_fast(iv0) * tanhf_fast(gv0);
            float cn1 = sigmoidf_fast(fv1) * (cp.y * em) + sigmoidf_fast(iv1) * tanhf_fast(gv1);
            float hn0 = sigmoidf_fast(ov0) * tanhf_fast(cn0);
            float hn1 = sigmoidf_fast(ov1) * tanhf_fast(cn1);
            *(float2*)&g_c[row * HID + colb]   = make_float2(cn0, cn1);
            *(float2*)&h_out[row * HID + colb] = make_float2(f2tf32(hn0), f2tf32(hn1));
            *(float2*)&out_hs[((size_t)t * BATCH + row) * HID + colb] = make_float2(hn0, hn1);
        }

        grid_sync((unsigned)t);

        em0 = nem0; em1 = nem1;
#pragma unroll
        for (int gate = 0; gate < 4; gate++) {
            pG[gate][0] = nG[gate][0];
            pG[gate][1] = nG[gate][1];
        }
    }
}

// ---------------- final state writeback ----------------
// c from g_c; final h = full-precision hs[T-1] (already in out).

__global__ void write_final(float* __restrict__ out) {
    int idx = blockIdx.x * blockDim.x + threadIdx.x;
    if (idx < BATCH * HID) {
        int b = idx / HID, j = idx % HID;
        size_t base = (size_t)T_STEPS * BATCH * HID;
        out[base + (size_t)b * 2 * HID + j] = g_c[idx];
        out[base + (size_t)b * 2 * HID + HID + j] =
            out[(size_t)(T_STEPS - 1) * BATCH * HID + (size_t)b * HID + j];
    }
}

// ---------------- launch ----------------

extern "C" void kernel_launch(void* const* d_in, const int* in_sizes, int n_in,
                              void* d_out, int out_size) {
    const float* x    = (const float*)d_in[0];  // [T,B,D]
    const float* mask = (const float*)d_in[1];  // [T,B,1]
    const float* csh  = (const float*)d_in[2];  // [B,2H]
    const float* Wx   = (const float*)d_in[3];  // [D,4H]
    const float* Wh   = (const float*)d_in[4];  // [H,4H]
    const float* bias = (const float*)d_in[5];  // [4H]
    float* out = (float*)d_out;

    cudaFuncSetAttribute(lstm_persistent,
                         cudaFuncAttributeMaxDynamicSharedMemorySize, LS_SMEM_BYTES);
    cudaFuncSetAttribute(pregemm,
                         cudaFuncAttributeMaxDynamicSharedMemorySize, PG_SMEM_BYTES);

    init_state<<<(BATCH * HID + 255) / 256, 256>>>(csh);

    prep_xA<<<dim3(DIN / 32, (T_STEPS * BATCH) / 128), 256>>>(x);
    prep_WxB<<<dim3(NGATE / 128, DIN / 32), 256>>>(Wx);

    pregemm<<<dim3(NGATE / 128, (T_STEPS * BATCH) / 128), 256, PG_SMEM_BYTES>>>(bias);

    lstm_persistent<<<NBLK, 256, LS_SMEM_BYTES>>>(mask, Wh, out);

    write_final<<<(BATCH * HID + 255) / 256, 256>>>(out);
}

// round 9
// speedup vs baseline: 1.4990x; 1.4990x over previous
#include <cuda_runtime.h>
#include <cstdint>

#define T_STEPS 256
#define BATCH   128
#define DIN     1024
#define HID     1024
#define NGATE   4096  // 4*HID
#define NBLK    128

// Scratch (device globals; no allocation allowed in kernel_launch).
__device__ float g_G[(size_t)T_STEPS * BATCH * NGATE];   // x@Wx + b (512 MB)
__device__ float g_xA[(size_t)T_STEPS * BATCH * DIN];    // x, tf32-rounded, A-fragment order (128 MB)
__device__ float g_WxB[(size_t)DIN * NGATE];             // Wx, tf32-rounded, B-fragment order (16 MB)
__device__ float g_h[2][BATCH * HID];                    // double-buffered hidden state
__device__ float g_c[BATCH * HID];                       // cell state
__device__ unsigned g_cnt;                               // barrier arrive counter
__device__ volatile unsigned g_gen;                      // barrier generation

// ---------------- helpers ----------------

__device__ __forceinline__ float f2tf32(float x) {
    uint32_t u;
    asm("cvt.rna.tf32.f32 %0, %1;" : "=r"(u) : "f"(x));
    return __uint_as_float(u);
}

__device__ __forceinline__ void mma_tf32(float c[4], const uint32_t a[4], const uint32_t b[2]) {
    asm volatile(
        "mma.sync.aligned.m16n8k8.row.col.f32.tf32.tf32.f32 "
        "{%0,%1,%2,%3}, {%4,%5,%6,%7}, {%8,%9}, {%0,%1,%2,%3};"
        : "+f"(c[0]), "+f"(c[1]), "+f"(c[2]), "+f"(c[3])
        : "r"(a[0]), "r"(a[1]), "r"(a[2]), "r"(a[3]), "r"(b[0]), "r"(b[1]));
}

__device__ __forceinline__ void cp_async16(uint32_t dst_smem, const void* src) {
    asm volatile("cp.async.ca.shared.global [%0], [%1], 16;" :: "r"(dst_smem), "l"(src));
}

__device__ __forceinline__ float sigmoidf_fast(float x) {
    x = fminf(fmaxf(x, -30.f), 30.f);
    return __fdividef(1.f, 1.f + __expf(-x));
}

__device__ __forceinline__ float tanhf_fast(float x) {
    x = fminf(fmaxf(x, -15.f), 15.f);
    float e = __expf(2.f * x);
    return __fdividef(e - 1.f, e + 1.f);
}

// Software grid barrier. All NBLK blocks co-resident (1 block/SM, 128<148).
__device__ __forceinline__ void grid_sync(unsigned step) {
    __syncthreads();
    if (threadIdx.x == 0) {
        __threadfence();
        unsigned a = atomicAdd(&g_cnt, 1u);
        if (a == gridDim.x - 1) {
            g_cnt = 0;
            __threadfence();
            g_gen = step + 1;
        } else {
            while (g_gen < step + 1) __nanosleep(32);
        }
        __threadfence();
    }
    __syncthreads();
}

// ---------------- init state + barrier ----------------

__global__ void init_state(const float* __restrict__ csh) {
    int idx = blockIdx.x * blockDim.x + threadIdx.x;
    if (idx == 0) { g_cnt = 0; g_gen = 0; }
    if (idx < BATCH * HID) {
        int b = idx / HID, j = idx % HID;
        g_c[idx]    = csh[b * 2 * HID + j];          // cell first
        g_h[0][idx] = csh[b * 2 * HID + HID + j];    // hidden second
    }
}

// ---------------- prep: permute+round x and Wx into fragment tile order ----

__global__ void prep_xA(const float* __restrict__ x) {
    __shared__ float tl[128 * 33];
    int ki = blockIdx.x, mi = blockIdx.y;
    int tid = threadIdx.x;  // 256
    for (int i = 0; i < 16; i++) {
        int e = tid + i * 256, r = e >> 5, c = e & 31;
        tl[r * 33 + c] = x[(size_t)(mi * 128 + r) * DIN + ki * 32 + c];
    }
    __syncthreads();
    size_t base = ((size_t)mi * 32 + ki) << 12;  // *4096
    for (int i = 0; i < 4; i++) {
        int o = tid + i * 256;           // float4 index 0..1023
        int lane = o & 31, mt = (o >> 5) & 1, wm = (o >> 6) & 3, k8 = o >> 8;
        int g = lane >> 2, t4 = lane & 3;
        int r0 = wm * 32 + mt * 16 + g, r1 = r0 + 8;
        int ka = k8 * 8 + t4, kb = ka + 4;
        float4 v;
        v.x = f2tf32(tl[r0 * 33 + ka]);
        v.y = f2tf32(tl[r1 * 33 + ka]);
        v.z = f2tf32(tl[r0 * 33 + kb]);
        v.w = f2tf32(tl[r1 * 33 + kb]);
        ((float4*)(g_xA + base))[o] = v;
    }
}

__global__ void prep_WxB(const float* __restrict__ Wx) {
    __shared__ float tl[32 * 129];
    int ni = blockIdx.x, ki = blockIdx.y;
    int tid = threadIdx.x;  // 256
    for (int i = 0; i < 16; i++) {
        int e = tid + i * 256, r = e >> 7, c = e & 127;
        tl[r * 129 + c] = Wx[(size_t)(ki * 32 + r) * NGATE + ni * 128 + c];
    }
    __syncthreads();
    size_t base = ((size_t)ki * 32 + ni) << 12;
    for (int i = 0; i < 4; i++) {
        int o = tid + i * 256;
        int lane = o & 31, w = (o >> 5) & 3, wn = (o >> 7) & 1, k8 = o >> 8;
        int g = lane >> 2, t4 = lane & 3;
        int c0 = wn * 64 + (2 * w) * 8 + g, c1 = c0 + 8;
        int ka = k8 * 8 + t4, kb = ka + 4;
        float4 v;
        v.x = f2tf32(tl[ka * 129 + c0]);
        v.y = f2tf32(tl[kb * 129 + c0]);
        v.z = f2tf32(tl[ka * 129 + c1]);
        v.w = f2tf32(tl[kb * 129 + c1]);
        ((float4*)(g_WxB + base))[o] = v;
    }
}

// ---------------- pre-GEMM: G = x @ Wx + bias ----------------
// Tile 128x128x32; fragment-ordered tiles; 6 LDS.128 per 16 mma; 3-stage cp.async.

#define PG_STAGE_FLOATS 8192       // A 4096 + B 4096 = 32 KB
#define PG_STAGES 3
#define PG_SMEM_BYTES (PG_STAGES * PG_STAGE_FLOATS * 4)  // 96 KB

__device__ __forceinline__ void pg_fill(uint32_t sstage, int mi, int ni, int kt, int tid) {
#pragma unroll
    for (int i = 0; i < 4; i++) {
        int o = tid + i * 256;
        cp_async16(sstage + (uint32_t)o * 16, g_xA + (((size_t)mi * 32 + kt) << 12) + o * 4);
    }
#pragma unroll
    for (int i = 0; i < 4; i++) {
        int o = tid + i * 256;
        cp_async16(sstage + 16384 + (uint32_t)o * 16, g_WxB + (((size_t)kt * 32 + ni) << 12) + o * 4);
    }
}

__global__ __launch_bounds__(256, 2) void pregemm(const float* __restrict__ bias) {
    extern __shared__ float sm[];
    const uint32_t sbase = (uint32_t)__cvta_generic_to_shared(sm);

    const int tid  = threadIdx.x;
    const int warp = tid >> 5, lane = tid & 31;
    const int g  = lane >> 2, t4 = lane & 3;
    const int wm = warp >> 1, wn = warp & 1;
    const int ni = blockIdx.x, mi = blockIdx.y;
    const int m0 = mi * 128, n0 = ni * 128;

    float acc[2][8][4];
#pragma unroll
    for (int a = 0; a < 2; a++)
#pragma unroll
        for (int b = 0; b < 8; b++)
#pragma unroll
            for (int c = 0; c < 4; c++) acc[a][b][c] = 0.f;

    pg_fill(sbase, mi, ni, 0, tid);
    asm volatile("cp.async.commit_group;");
    pg_fill(sbase + PG_STAGE_FLOATS * 4, mi, ni, 1, tid);
    asm volatile("cp.async.commit_group;");

    for (int kt = 0; kt < 32; kt++) {
        asm volatile("cp.async.wait_group 1;");
        __syncthreads();

        if (kt + 2 < 32)
            pg_fill(sbase + (uint32_t)((kt + 2) % PG_STAGES) * PG_STAGE_FLOATS * 4,
                    mi, ni, kt + 2, tid);
        asm volatile("cp.async.commit_group;");

        const float* st  = sm + (kt % PG_STAGES) * PG_STAGE_FLOATS;
        const float* stA = st;
        const float* stB = st + 4096;
#pragma unroll
        for (int k8 = 0; k8 < 4; k8++) {
            float4 fa0 = *(const float4*)&stA[k8 * 1024 + wm * 256 + lane * 4];
            float4 fa1 = *(const float4*)&stA[k8 * 1024 + wm * 256 + 128 + lane * 4];
            uint32_t a0[4] = {__float_as_uint(fa0.x), __float_as_uint(fa0.y),
                              __float_as_uint(fa0.z), __float_as_uint(fa0.w)};
            uint32_t a1[4] = {__float_as_uint(fa1.x), __float_as_uint(fa1.y),
                              __float_as_uint(fa1.z), __float_as_uint(fa1.w)};
#pragma unroll
            for (int w = 0; w < 4; w++) {
                float4 fb = *(const float4*)&stB[k8 * 1024 + wn * 512 + w * 128 + lane * 4];
                uint32_t b0[2] = {__float_as_uint(fb.x), __float_as_uint(fb.y)};
                uint32_t b1[2] = {__float_as_uint(fb.z), __float_as_uint(fb.w)};
                mma_tf32(acc[0][2 * w],     a0, b0);
                mma_tf32(acc[1][2 * w],     a1, b0);
                mma_tf32(acc[0][2 * w + 1], a0, b1);
                mma_tf32(acc[1][2 * w + 1], a1, b1);
            }
        }
    }

#pragma unroll
    for (int mt = 0; mt < 2; mt++) {
#pragma unroll
        for (int nt = 0; nt < 8; nt++) {
            int r = m0 + wm * 32 + mt * 16 + g;
            int c = n0 + wn * 64 + nt * 8 + 2 * t4;
            float b0 = bias[c], b1 = bias[c + 1];
            float2 v0 = make_float2(acc[mt][nt][0] + b0, acc[mt][nt][1] + b1);
            float2 v1 = make_float2(acc[mt][nt][2] + b0, acc[mt][nt][3] + b1);
            *(float2*)&g_G[(size_t)r * NGATE + c]       = v0;
            *(float2*)&g_G[(size_t)(r + 8) * NGATE + c] = v1;
        }
    }
}

// ---------------- persistent recurrence (R5 best-passing, verbatim) ----------------
// 128 blocks, 256 threads (8 warps). Block b owns gate-columns [8b, 8b+8) of
// each gate. Wh fragments resident in SMEM; per-warp double-buffered A staging,
// syncwarp-only mainloop; G[t+1]/mask[t+1] prefetched mid-loop.

#define A_STRIDE 68              // 64 + 4 pad, conflict-free frag loads
#define A_BUF    (16 * A_STRIDE) // 1088 floats per buffer
#define BFRAG_FLOATS 32768       // 128 kblocks * 256
#define SMEM_FLOATS (BFRAG_FLOATS + 8 * 2 * A_BUF)

__global__ __launch_bounds__(256, 1) void lstm_persistent(
        const float* __restrict__ mask,
        const float* __restrict__ Wh,
        float* __restrict__ out_hs) {
    extern __shared__ float smem[];
    float* Bfrag = smem;                 // 128 KB
    float* Ast   = smem + BFRAG_FLOATS;  // 8 warps * 2 bufs * 1088 floats

    const int tid  = threadIdx.x;
    const int warp = tid >> 5, lane = tid & 31;
    const int g  = lane >> 2, t4 = lane & 3;
    const int j0 = blockIdx.x * 8;
    const int rb = warp * 16;
    const int hi = lane >> 4;            // staging row parity
    const int colb = j0 + 2 * t4;        // even column base for float2 epilogue
    float* Aw = Ast + warp * 2 * A_BUF;

    for (int idx = tid; idx < BFRAG_FLOATS; idx += 256) {
        int kb     = idx >> 8;
        int within = idx & 255;
        int q      = within >> 7;
        int rest   = within & 127;
        int lane_i = rest >> 2;
        int sub    = rest & 3;
        int gate   = q * 2 + (sub >> 1);
        int s      = sub & 1;
        int g8     = lane_i >> 2;
        int t4v    = lane_i & 3;
        int k      = kb * 8 + s * 4 + t4v;
        Bfrag[idx] = f2tf32(Wh[(size_t)k * NGATE + gate * HID + j0 + g8]);
    }
    __syncthreads();

    float msk[8], emsk0, emsk1;
    float2 pG[4][2];
    {
        const float* mrow = mask;
#pragma unroll
        for (int i = 0; i < 8; i++) msk[i] = 1.0f - __ldg(&mrow[rb + 2 * i + hi]);
        emsk0 = 1.0f - __ldg(&mrow[rb + g]);
        emsk1 = 1.0f - __ldg(&mrow[rb + g + 8]);
#pragma unroll
        for (int r = 0; r < 2; r++) {
            size_t gb = ((size_t)(rb + g + r * 8)) * NGATE + colb;
#pragma unroll
            for (int gate = 0; gate < 4; gate++)
                pG[gate][r] = __ldg((const float2*)&g_G[gb + gate * HID]);
        }
    }

    for (int t = 0; t < T_STEPS; t++) {
        const float* __restrict__ h_in  = g_h[t & 1];
        float*       __restrict__ h_out = g_h[(t + 1) & 1];

        float nmsk[8] = {0.f, 0.f, 0.f, 0.f, 0.f, 0.f, 0.f, 0.f};
        float nem0 = 0.f, nem1 = 0.f;
        float2 nG[4][2];
#pragma unroll
        for (int gate = 0; gate < 4; gate++) {
            nG[gate][0] = make_float2(0.f, 0.f);
            nG[gate][1] = make_float2(0.f, 0.f);
        }

        float acc[4][4];
#pragma unroll
        for (int a = 0; a < 4; a++)
#pragma unroll
            for (int c = 0; c < 4; c++) acc[a][c] = 0.f;

        float4 ld[8];
#pragma unroll
        for (int i = 0; i < 8; i++) {
            int f = i * 32 + lane;
            int row = f >> 4, quad = f & 15;
            ld[i] = *(const float4*)&h_in[(rb + row) * HID + quad * 4];
        }
#pragma unroll
        for (int i = 0; i < 8; i++) {
            int f = i * 32 + lane;
            int row = f >> 4, quad = f & 15;
            float4 v = ld[i];
            float sc = msk[i];
            v.x = f2tf32(v.x * sc); v.y = f2tf32(v.y * sc);
            v.z = f2tf32(v.z * sc); v.w = f2tf32(v.w * sc);
            *(float4*)&Aw[row * A_STRIDE + quad * 4] = v;
        }
        __syncwarp();

        for (int c = 0; c < 16; c++) {
            const uint32_t* Au = (const uint32_t*)(Aw + (c & 1) * A_BUF);
            if (c < 15) {
#pragma unroll
                for (int i = 0; i < 8; i++) {
                    int f = i * 32 + lane;
                    int row = f >> 4, quad = f & 15;
                    ld[i] = *(const float4*)&h_in[(rb + row) * HID + (c + 1) * 64 + quad * 4];
                }
            }
            if (c == 7 && t + 1 < T_STEPS) {
                const float* nmrow = mask + (size_t)(t + 1) * BATCH;
#pragma unroll
                for (int i = 0; i < 8; i++) nmsk[i] = 1.0f - __ldg(&nmrow[rb + 2 * i + hi]);
                nem0 = 1.0f - __ldg(&nmrow[rb + g]);
                nem1 = 1.0f - __ldg(&nmrow[rb + g + 8]);
#pragma unroll
                for (int r = 0; r < 2; r++) {
                    size_t gb = ((size_t)(t + 1) * BATCH + rb + g + r * 8) * NGATE + colb;
#pragma unroll
                    for (int gate = 0; gate < 4; gate++)
                        nG[gate][r] = __ldg((const float2*)&g_G[gb + gate * HID]);
                }
            }
#pragma unroll
            for (int kb8 = 0; kb8 < 8; kb8++) {
                int kk = kb8 * 8;
                uint32_t afr[4];
                afr[0] = Au[g * A_STRIDE + kk + t4];
                afr[1] = Au[(g + 8) * A_STRIDE + kk + t4];
                afr[2] = Au[g * A_STRIDE + kk + t4 + 4];
                afr[3] = Au[(g + 8) * A_STRIDE + kk + t4 + 4];
                const float* Bb = Bfrag + (c * 8 + kb8) * 256;
                float4 bA = *(const float4*)&Bb[lane * 4];        // gates 0,1
                float4 bB = *(const float4*)&Bb[128 + lane * 4];  // gates 2,3
                uint32_t b0[2] = {__float_as_uint(bA.x), __float_as_uint(bA.y)};
                uint32_t b1[2] = {__float_as_uint(bA.z), __float_as_uint(bA.w)};
                uint32_t b2[2] = {__float_as_uint(bB.x), __float_as_uint(bB.y)};
                uint32_t b3[2] = {__float_as_uint(bB.z), __float_as_uint(bB.w)};
                mma_tf32(acc[0], afr, b0);
                mma_tf32(acc[1], afr, b1);
                mma_tf32(acc[2], afr, b2);
                mma_tf32(acc[3], afr, b3);
            }
            if (c < 15) {
                float* An = Aw + ((c + 1) & 1) * A_BUF;
#pragma unroll
                for (int i = 0; i < 8; i++) {
                    int f = i * 32 + lane;
                    int row = f >> 4, quad = f & 15;
                    float4 v = ld[i];
                    float sc = msk[i];
                    v.x = f2tf32(v.x * sc); v.y = f2tf32(v.y * sc);
                    v.z = f2tf32(v.z * sc); v.w = f2tf32(v.w * sc);
                    *(float4*)&An[row * A_STRIDE + quad * 4] = v;
                }
            }
            __syncwarp();
        }

#pragma unroll
        for (int r = 0; r < 2; r++) {
            int row = rb + g + r * 8;
            float em = r ? emsk1 : emsk0;
            float2 cp = *(const float2*)&g_c[row * HID + colb];
            float iv0 = acc[0][2 * r]     + pG[0][r].x;
            float iv1 = acc[0][2 * r + 1] + pG[0][r].y;
            float fv0 = acc[1][2 * r]     + pG[1][r].x;
            float fv1 = acc[1][2 * r + 1] + pG[1][r].y;
            float ov0 = acc[2][2 * r]     + pG[2][r].x;
            float ov1 = acc[2][2 * r + 1] + pG[2][r].y;
            float gv0 = acc[3][2 * r]     + pG[3][r].x;
            float gv1 = acc[3][2 * r + 1] + pG[3][r].y;
            float cn0 = sigmoidf_fast(fv0) * (cp.x * em) + sigmoidf_fast(iv0) * tanhf_fast(gv0);
            float cn1 = sigmoidf_fast(fv1) * (cp.y * em) + sigmoidf_fast(iv1) * tanhf_fast(gv1);
            float hn0 = sigmoidf_fast(ov0) * tanhf_fast(cn0);
            float hn1 = sigmoidf_fast(ov1) * tanhf_fast(cn1);
            *(float2*)&g_c[row * HID + colb]   = make_float2(cn0, cn1);
            *(float2*)&h_out[row * HID + colb] = make_float2(hn0, hn1);
            *(float2*)&out_hs[((size_t)t * BATCH + row) * HID + colb] = make_float2(hn0, hn1);
        }

        grid_sync((unsigned)t);

#pragma unroll
        for (int i = 0; i < 8; i++) msk[i] = nmsk[i];
        emsk0 = nem0; emsk1 = nem1;
#pragma unroll
        for (int gate = 0; gate < 4; gate++) {
            pG[gate][0] = nG[gate][0];
            pG[gate][1] = nG[gate][1];
        }
    }
}

// ---------------- final state writeback ----------------

__global__ void write_final(float* __restrict__ out) {
    int idx = blockIdx.x * blockDim.x + threadIdx.x;
    if (idx < BATCH * HID) {
        int b = idx / HID, j = idx % HID;
        size_t base = (size_t)T_STEPS * BATCH * HID;
        out[base + (size_t)b * 2 * HID + j]       = g_c[idx];
        out[base + (size_t)b * 2 * HID + HID + j] = g_h[T_STEPS & 1][idx];
    }
}

// ---------------- launch ----------------

extern "C" void kernel_launch(void* const* d_in, const int* in_sizes, int n_in,
                              void* d_out, int out_size) {
    const float* x    = (const float*)d_in[0];  // [T,B,D]
    const float* mask = (const float*)d_in[1];  // [T,B,1]
    const float* csh  = (const float*)d_in[2];  // [B,2H]
    const float* Wx   = (const float*)d_in[3];  // [D,4H]
    const float* Wh   = (const float*)d_in[4];  // [H,4H]
    const float* bias = (const float*)d_in[5];  // [4H]
    float* out = (float*)d_out;

    cudaFuncSetAttribute(lstm_persistent,
                         cudaFuncAttributeMaxDynamicSharedMemorySize,
                         SMEM_FLOATS * (int)sizeof(float));
    cudaFuncSetAttribute(pregemm,
                         cudaFuncAttributeMaxDynamicSharedMemorySize, PG_SMEM_BYTES);

    init_state<<<(BATCH * HID + 255) / 256, 256>>>(csh);

    prep_xA<<<dim3(DIN / 32, (T_STEPS * BATCH) / 128), 256>>>(x);
    prep_WxB<<<dim3(NGATE / 128, DIN / 32), 256>>>(Wx);

    pregemm<<<dim3(NGATE / 128, (T_STEPS * BATCH) / 128), 256, PG_SMEM_BYTES>>>(bias);

    lstm_persistent<<<NBLK, 256, SMEM_FLOATS * sizeof(float)>>>(mask, Wh, out);

    write_final<<<(BATCH * HID + 255) / 256, 256>>>(out);
}